// round 2
// baseline (speedup 1.0000x reference)
#include <cuda_runtime.h>
#include <cuda_bf16.h>

// Problem constants (fixed shapes per reference)
#define N_NODES   50000
#define IN_FEATS  256
#define OUT_FEATS 128

// Scratch: projected features hw = h @ W  (25.6 MB)
__device__ float g_hw[(size_t)N_NODES * OUT_FEATS];

// ---------------------------------------------------------------------------
// Kernel 1: SGEMM  hw[M,128] = h[M,256] @ W[256,128]
// Block: 256 threads computes a 64x128 tile. Thread micro-tile: 8 rows x 4 cols.
// ---------------------------------------------------------------------------
#define BM 64
#define BN 128
#define BK 32

__global__ __launch_bounds__(256) void gemm_kernel(
    const float* __restrict__ h, const float* __restrict__ W, int M)
{
    __shared__ float As[BM][BK + 4];
    __shared__ float Bs[BK][BN];

    const int tid = threadIdx.x;
    const int tx  = tid & 31;   // col group: 32 groups of 4 cols
    const int ty  = tid >> 5;   // row group: 8 groups of 8 rows
    const int block_m = blockIdx.x * BM;

    float acc[8][4];
#pragma unroll
    for (int i = 0; i < 8; i++)
#pragma unroll
        for (int j = 0; j < 4; j++) acc[i][j] = 0.f;

    for (int k0 = 0; k0 < IN_FEATS; k0 += BK) {
        // Load A tile: 64 rows x 32 cols = 512 float4, 2 per thread.
#pragma unroll
        for (int l = 0; l < 2; l++) {
            int idx = tid + l * 256;
            int r = idx >> 3;          // 0..63
            int c4 = idx & 7;          // 0..7 (float4 within row)
            int gr = block_m + r;
            float4 v = make_float4(0.f, 0.f, 0.f, 0.f);
            if (gr < M)
                v = *reinterpret_cast<const float4*>(h + (size_t)gr * IN_FEATS + k0 + c4 * 4);
            *reinterpret_cast<float4*>(&As[r][c4 * 4]) = v;
        }
        // Load B tile: 32 rows x 128 cols = 1024 float4, 4 per thread.
#pragma unroll
        for (int l = 0; l < 4; l++) {
            int idx = tid + l * 256;
            int r = idx >> 5;          // 0..31
            int c4 = idx & 31;         // 0..31
            *reinterpret_cast<float4*>(&Bs[r][c4 * 4]) =
                *reinterpret_cast<const float4*>(W + (size_t)(k0 + r) * BN + c4 * 4);
        }
        __syncthreads();

#pragma unroll
        for (int k = 0; k < BK; k++) {
            float4 b = *reinterpret_cast<const float4*>(&Bs[k][tx * 4]);
            float a[8];
#pragma unroll
            for (int i = 0; i < 8; i++) a[i] = As[ty * 8 + i][k];
#pragma unroll
            for (int i = 0; i < 8; i++) {
                acc[i][0] = fmaf(a[i], b.x, acc[i][0]);
                acc[i][1] = fmaf(a[i], b.y, acc[i][1]);
                acc[i][2] = fmaf(a[i], b.z, acc[i][2]);
                acc[i][3] = fmaf(a[i], b.w, acc[i][3]);
            }
        }
        __syncthreads();
    }

#pragma unroll
    for (int i = 0; i < 8; i++) {
        int gr = block_m + ty * 8 + i;
        if (gr < M)
            *reinterpret_cast<float4*>(&g_hw[(size_t)gr * BN + tx * 4]) =
                make_float4(acc[i][0], acc[i][1], acc[i][2], acc[i][3]);
    }
}

// ---------------------------------------------------------------------------
// Kernel 2: per-edge scatter. One warp per edge.
// Indices are int32 (JAX x64 disabled downgrades int64 -> int32).
// Each lane handles a float4 of the 128-wide feature: gather hw[src] (L2 hit),
// scale by norm[src]*edge_weight, vector-reduce into out[dst].
// ---------------------------------------------------------------------------
__global__ __launch_bounds__(256) void scatter_kernel(
    const float* __restrict__ norm, const float* __restrict__ ew,
    const int* __restrict__ src, const int* __restrict__ dst,
    float* __restrict__ out, int E, int N)
{
    int e = blockIdx.x * (blockDim.x >> 5) + (threadIdx.x >> 5);
    if (e >= E) return;
    int lane = threadIdx.x & 31;

    int s = src[e];
    int d = dst[e];
    // Defensive bounds guard: if dtype assumption is ever wrong we fail with
    // a wrong answer (diagnosable) rather than an illegal access.
    if ((unsigned)s >= (unsigned)N || (unsigned)d >= (unsigned)N) return;

    float c = norm[s] * ew[e];

    float4 v = *reinterpret_cast<const float4*>(&g_hw[(size_t)s * OUT_FEATS + lane * 4]);
    v.x *= c; v.y *= c; v.z *= c; v.w *= c;

    float* p = out + (size_t)d * OUT_FEATS + lane * 4;
    asm volatile("red.global.add.v4.f32 [%0], {%1, %2, %3, %4};"
                 :: "l"(p), "f"(v.x), "f"(v.y), "f"(v.z), "f"(v.w)
                 : "memory");
}

// ---------------------------------------------------------------------------
// Kernel 3: out = relu(agg * norm[dst] + bias), in place, float4 grain.
// ---------------------------------------------------------------------------
__global__ __launch_bounds__(256) void finalize_kernel(
    float* __restrict__ out, const float* __restrict__ norm,
    const float* __restrict__ bias, int N)
{
    int i = blockIdx.x * blockDim.x + threadIdx.x;  // over N*32 float4s
    int total = N * (OUT_FEATS / 4);
    if (i >= total) return;
    int node = i >> 5;       // /32 float4s per row
    int c4   = i & 31;

    float4 v = reinterpret_cast<float4*>(out)[i];
    float  n = norm[node];
    float4 b = reinterpret_cast<const float4*>(bias)[c4];
    v.x = fmaxf(fmaf(v.x, n, b.x), 0.f);
    v.y = fmaxf(fmaf(v.y, n, b.y), 0.f);
    v.z = fmaxf(fmaf(v.z, n, b.z), 0.f);
    v.w = fmaxf(fmaf(v.w, n, b.w), 0.f);
    reinterpret_cast<float4*>(out)[i] = v;
}

// ---------------------------------------------------------------------------
// Launch: inputs are h, weight, bias, norm, edge_weight, edge_src, edge_dst
// ---------------------------------------------------------------------------
extern "C" void kernel_launch(void* const* d_in, const int* in_sizes, int n_in,
                              void* d_out, int out_size)
{
    const float* h    = (const float*)d_in[0];
    const float* W    = (const float*)d_in[1];
    const float* bias = (const float*)d_in[2];
    const float* norm = (const float*)d_in[3];
    const float* ew   = (const float*)d_in[4];
    const int*   src  = (const int*)d_in[5];
    const int*   dst  = (const int*)d_in[6];
    float* out = (float*)d_out;

    const int N = in_sizes[3];   // 50000 nodes
    const int E = in_sizes[4];   // 800000 edges

    // d_out is poisoned each replay; zero it (aggregation target).
    cudaMemsetAsync(out, 0, (size_t)out_size * sizeof(float));

    // 1) hw = h @ W
    gemm_kernel<<<(N + BM - 1) / BM, 256>>>(h, W, N);

    // 2) edge scatter with vector atomics
    int warps_per_block = 256 / 32;
    int blocks = (E + warps_per_block - 1) / warps_per_block;
    scatter_kernel<<<blocks, 256>>>(norm, ew, src, dst, out, E, N);

    // 3) scale + bias + relu
    int total4 = N * (OUT_FEATS / 4);
    finalize_kernel<<<(total4 + 255) / 256, 256>>>(out, norm, bias, N);
}

// round 3
// speedup vs baseline: 1.3295x; 1.3295x over previous
#include <cuda_runtime.h>
#include <cuda_bf16.h>

#define N_NODES   50000
#define IN_FEATS  256
#define OUT_FEATS 128
#define MAX_E     800000

// ---- scratch (device globals; no allocs allowed) ----
__device__ float g_hw[(size_t)N_NODES * OUT_FEATS];   // projected features
__device__ int   g_counts[N_NODES];                   // in-degree histogram
__device__ int   g_row_ptr[N_NODES + 1];              // CSR row offsets (by dst)
__device__ int   g_cursor[N_NODES];                   // fill cursors
__device__ int   g_bsum[256];                         // scan block sums
__device__ int   g_boff[256];                         // scanned block offsets
__device__ int   g_perm_src[MAX_E];                   // src per CSR slot
__device__ float g_perm_c[MAX_E];                     // coeff per CSR slot

// ===========================================================================
// Kernel 1: SGEMM hw[M,128] = h[M,256] @ W[256,128]
// 128x128 block tile, BK=16, 256 threads, 8x8 micro-tile, A transposed in smem.
// ===========================================================================
#define GBM 128
#define GBN 128
#define GBK 16

__global__ __launch_bounds__(256) void gemm_kernel(
    const float* __restrict__ h, const float* __restrict__ W, int M)
{
    __shared__ float As[GBK][GBM + 4];   // K-major: As[k][m]
    __shared__ float Bs[GBK][GBN];

    const int tid  = threadIdx.x;
    const int tcol = tid & 15;    // 0..15 -> output cols tcol*8..+7
    const int trow = tid >> 4;    // 0..15 -> output rows trow*8..+7
    const int block_m = blockIdx.x * GBM;

    float acc[8][8];
#pragma unroll
    for (int i = 0; i < 8; i++)
#pragma unroll
        for (int j = 0; j < 8; j++) acc[i][j] = 0.f;

    for (int k0 = 0; k0 < IN_FEATS; k0 += GBK) {
        // A tile: 128 rows x 16 cols = 512 float4; 2 per thread. Transpose into As.
#pragma unroll
        for (int l = 0; l < 2; l++) {
            int idx = tid + l * 256;       // 0..511
            int r   = idx >> 2;            // 0..127
            int c4  = idx & 3;             // float4 index within the 16-wide row
            int gr  = block_m + r;
            float4 v = make_float4(0.f, 0.f, 0.f, 0.f);
            if (gr < M)
                v = *reinterpret_cast<const float4*>(h + (size_t)gr * IN_FEATS + k0 + c4 * 4);
            As[c4 * 4 + 0][r] = v.x;
            As[c4 * 4 + 1][r] = v.y;
            As[c4 * 4 + 2][r] = v.z;
            As[c4 * 4 + 3][r] = v.w;
        }
        // B tile: 16 rows x 128 cols = 512 float4; 2 per thread.
#pragma unroll
        for (int l = 0; l < 2; l++) {
            int idx = tid + l * 256;
            int r   = idx >> 5;            // 0..15
            int c4  = idx & 31;            // 0..31
            *reinterpret_cast<float4*>(&Bs[r][c4 * 4]) =
                *reinterpret_cast<const float4*>(W + (size_t)(k0 + r) * GBN + c4 * 4);
        }
        __syncthreads();

#pragma unroll
        for (int k = 0; k < GBK; k++) {
            float4 a0 = *reinterpret_cast<const float4*>(&As[k][trow * 8]);
            float4 a1 = *reinterpret_cast<const float4*>(&As[k][trow * 8 + 4]);
            float4 b0 = *reinterpret_cast<const float4*>(&Bs[k][tcol * 8]);
            float4 b1 = *reinterpret_cast<const float4*>(&Bs[k][tcol * 8 + 4]);
            float a[8] = {a0.x, a0.y, a0.z, a0.w, a1.x, a1.y, a1.z, a1.w};
            float b[8] = {b0.x, b0.y, b0.z, b0.w, b1.x, b1.y, b1.z, b1.w};
#pragma unroll
            for (int i = 0; i < 8; i++)
#pragma unroll
                for (int j = 0; j < 8; j++)
                    acc[i][j] = fmaf(a[i], b[j], acc[i][j]);
        }
        __syncthreads();
    }

#pragma unroll
    for (int i = 0; i < 8; i++) {
        int gr = block_m + trow * 8 + i;
        if (gr < M) {
            *reinterpret_cast<float4*>(&g_hw[(size_t)gr * GBN + tcol * 8]) =
                make_float4(acc[i][0], acc[i][1], acc[i][2], acc[i][3]);
            *reinterpret_cast<float4*>(&g_hw[(size_t)gr * GBN + tcol * 8 + 4]) =
                make_float4(acc[i][4], acc[i][5], acc[i][6], acc[i][7]);
        }
    }
}

// ===========================================================================
// CSR build
// ===========================================================================
__global__ void zero_counts_kernel(int N)
{
    int i = blockIdx.x * blockDim.x + threadIdx.x;
    if (i < N) g_counts[i] = 0;
}

__global__ void hist_kernel(const int* __restrict__ dst, int E)
{
    int e = blockIdx.x * blockDim.x + threadIdx.x;
    if (e < E) atomicAdd(&g_counts[dst[e]], 1);
}

// scan step 1: per-block (chunk=256) sums
__global__ __launch_bounds__(256) void scan_sums_kernel(int N)
{
    __shared__ int sh[256];
    int i = blockIdx.x * 256 + threadIdx.x;
    sh[threadIdx.x] = (i < N) ? g_counts[i] : 0;
    __syncthreads();
#pragma unroll
    for (int s = 128; s > 0; s >>= 1) {
        if (threadIdx.x < s) sh[threadIdx.x] += sh[threadIdx.x + s];
        __syncthreads();
    }
    if (threadIdx.x == 0) g_bsum[blockIdx.x] = sh[0];
}

// scan step 2: single block exclusive scan of block sums (nb <= 256)
__global__ __launch_bounds__(256) void scan_top_kernel(int nb, int N, int E)
{
    __shared__ int sh[256];
    int t = threadIdx.x;
    int v = (t < nb) ? g_bsum[t] : 0;
    sh[t] = v;
    __syncthreads();
    // Hillis-Steele inclusive scan
#pragma unroll
    for (int s = 1; s < 256; s <<= 1) {
        int add = (t >= s) ? sh[t - s] : 0;
        __syncthreads();
        sh[t] += add;
        __syncthreads();
    }
    if (t < nb) g_boff[t] = sh[t] - v;   // exclusive
    if (t == 0) g_row_ptr[N] = E;
}

// scan step 3: local exclusive scan + write row_ptr and cursor
__global__ __launch_bounds__(256) void scan_write_kernel(int N)
{
    __shared__ int sh[256];
    int t = threadIdx.x;
    int i = blockIdx.x * 256 + t;
    int v = (i < N) ? g_counts[i] : 0;
    sh[t] = v;
    __syncthreads();
#pragma unroll
    for (int s = 1; s < 256; s <<= 1) {
        int add = (t >= s) ? sh[t - s] : 0;
        __syncthreads();
        sh[t] += add;
        __syncthreads();
    }
    if (i < N) {
        int rp = g_boff[blockIdx.x] + sh[t] - v;   // exclusive prefix
        g_row_ptr[i] = rp;
        g_cursor[i]  = rp;
    }
}

// permutation: bucket edges by dst, precompute coefficient
__global__ void permute_kernel(
    const int* __restrict__ src, const int* __restrict__ dst,
    const float* __restrict__ norm, const float* __restrict__ ew, int E)
{
    int e = blockIdx.x * blockDim.x + threadIdx.x;
    if (e >= E) return;
    int s = src[e];
    int d = dst[e];
    int pos = atomicAdd(&g_cursor[d], 1);
    g_perm_src[pos] = s;
    g_perm_c[pos]   = norm[s] * ew[e];
}

// ===========================================================================
// Kernel: gather-aggregate per destination node + fused finalize.
// One warp per node; lane handles one float4 of the 128-wide feature.
// ===========================================================================
__global__ __launch_bounds__(256) void gather_kernel(
    const float* __restrict__ norm, const float* __restrict__ bias,
    float* __restrict__ out, int N)
{
    int d = blockIdx.x * 8 + (threadIdx.x >> 5);
    if (d >= N) return;
    int lane = threadIdx.x & 31;

    int j   = g_row_ptr[d];
    int end = g_row_ptr[d + 1];

    const float4* hw4 = reinterpret_cast<const float4*>(g_hw);
    float4 acc = make_float4(0.f, 0.f, 0.f, 0.f);

    for (; j + 2 <= end; j += 2) {
        int   s0 = g_perm_src[j],   s1 = g_perm_src[j + 1];
        float c0 = g_perm_c[j],     c1 = g_perm_c[j + 1];
        float4 v0 = hw4[(size_t)s0 * 32 + lane];
        float4 v1 = hw4[(size_t)s1 * 32 + lane];
        acc.x = fmaf(c0, v0.x, acc.x); acc.y = fmaf(c0, v0.y, acc.y);
        acc.z = fmaf(c0, v0.z, acc.z); acc.w = fmaf(c0, v0.w, acc.w);
        acc.x = fmaf(c1, v1.x, acc.x); acc.y = fmaf(c1, v1.y, acc.y);
        acc.z = fmaf(c1, v1.z, acc.z); acc.w = fmaf(c1, v1.w, acc.w);
    }
    if (j < end) {
        int   s0 = g_perm_src[j];
        float c0 = g_perm_c[j];
        float4 v0 = hw4[(size_t)s0 * 32 + lane];
        acc.x = fmaf(c0, v0.x, acc.x); acc.y = fmaf(c0, v0.y, acc.y);
        acc.z = fmaf(c0, v0.z, acc.z); acc.w = fmaf(c0, v0.w, acc.w);
    }

    float  nd = norm[d];
    float4 b  = reinterpret_cast<const float4*>(bias)[lane];
    float4 r;
    r.x = fmaxf(fmaf(acc.x, nd, b.x), 0.f);
    r.y = fmaxf(fmaf(acc.y, nd, b.y), 0.f);
    r.z = fmaxf(fmaf(acc.z, nd, b.z), 0.f);
    r.w = fmaxf(fmaf(acc.w, nd, b.w), 0.f);
    reinterpret_cast<float4*>(out)[(size_t)d * 32 + lane] = r;
}

// ===========================================================================
// Launch: h, weight, bias, norm, edge_weight, edge_src, edge_dst
// ===========================================================================
extern "C" void kernel_launch(void* const* d_in, const int* in_sizes, int n_in,
                              void* d_out, int out_size)
{
    const float* h    = (const float*)d_in[0];
    const float* W    = (const float*)d_in[1];
    const float* bias = (const float*)d_in[2];
    const float* norm = (const float*)d_in[3];
    const float* ew   = (const float*)d_in[4];
    const int*   src  = (const int*)d_in[5];
    const int*   dst  = (const int*)d_in[6];
    float* out = (float*)d_out;

    const int N  = in_sizes[3];
    const int E  = in_sizes[4];
    const int nb = (N + 255) / 256;

    // CSR build (by dst)
    zero_counts_kernel<<<nb, 256>>>(N);
    hist_kernel<<<(E + 255) / 256, 256>>>(dst, E);
    scan_sums_kernel<<<nb, 256>>>(N);
    scan_top_kernel<<<1, 256>>>(nb, N, E);
    scan_write_kernel<<<nb, 256>>>(N);
    permute_kernel<<<(E + 255) / 256, 256>>>(src, dst, norm, ew, E);

    // Dense projection
    gemm_kernel<<<(N + GBM - 1) / GBM, 256>>>(h, W, N);

    // Aggregate + finalize (writes every out row exactly once; no memset needed)
    gather_kernel<<<(N + 7) / 8, 256>>>(norm, bias, out, N);
}